// round 16
// baseline (speedup 1.0000x reference)
#include <cuda_runtime.h>
#include <math.h>
#include <stdint.h>

#define VOCAB 32000
#define DIM   1024
#define NBITS 15
#define NTOK  4096
#define KDIM  1024

#define OFF_BIT   4194304u
#define OFF_LOGIT 8388608u
#define OFF_LW    (8388608u + 131072000u)

// ---------------------------------------------------------------------------
// 1) id_emb
// ---------------------------------------------------------------------------
__global__ void id_embed_kernel(const int* __restrict__ ids,
                                const float* __restrict__ weight,
                                float* __restrict__ out)
{
    int idx = blockIdx.x * blockDim.x + threadIdx.x;
    int token = idx >> 8;
    int d4    = idx & 255;
    int id    = ids[token];
    id = min(max(id, 0), VOCAB - 1);
    const float4* src = reinterpret_cast<const float4*>(weight + (size_t)id * DIM);
    reinterpret_cast<float4*>(out)[idx] = src[d4];
}

// ---------------------------------------------------------------------------
// 2) bit_emb
// ---------------------------------------------------------------------------
__global__ void bit_embed_kernel(const int* __restrict__ ids,
                                 const float* __restrict__ wbit,
                                 float* __restrict__ out)
{
    int idx = blockIdx.x * blockDim.x + threadIdx.x;
    int token = idx >> 8;
    int d4    = idx & 255;
    int id    = ids[token];
    id = min(max(id, 0), VOCAB - 1);
    const float4* wb = reinterpret_cast<const float4*>(wbit);
    float4 acc = make_float4(0.f, 0.f, 0.f, 0.f);
#pragma unroll
    for (int j = 0; j < NBITS; j++) {
        float4 w = wb[j * 256 + d4];
        float s = ((id >> (14 - j)) & 1) ? 1.0f : -1.0f;
        acc.x += s * w.x; acc.y += s * w.y; acc.z += s * w.z; acc.w += s * w.w;
    }
    reinterpret_cast<float4*>(out)[idx] = acc;
}

// ---------------------------------------------------------------------------
// 3) GEMM: 3-pass split-bf16 m16n8k16 mma. BK=32 staging: two verified
//    R15 k16 sub-tiles per stage (identical per-subtile layout/offsets),
//    one __syncthreads per 2 k-tiles. 128x128 block, 8 warps, M-fast raster.
// ---------------------------------------------------------------------------
#define SSTR      12                  // u32 per row within a k16 subtile
#define SUB_BYTES (128 * SSTR * 4)    // 6144
#define ARR_BYTES (2 * SUB_BYTES)     // 12288 (k16 subtiles 0,1)
#define STG_BYTES (4 * ARR_BYTES)     // 49152 (Ah, Al, Bh, Bl)
#define GEMM_SMEM (2 * STG_BYTES)     // 98304
#define AH_OFF 0
#define AL_OFF ARR_BYTES
#define BH_OFF (2 * ARR_BYTES)
#define BL_OFF (3 * ARR_BYTES)

__device__ __forceinline__ uint32_t cvt_bf16x2(float hi, float lo) {
    uint32_t u;
    asm("cvt.rn.bf16x2.f32 %0, %1, %2;" : "=r"(u) : "f"(hi), "f"(lo));
    return u;
}
__device__ __forceinline__ void split4(float4 v, uint2& h, uint2& l) {
    h.x = cvt_bf16x2(v.y, v.x);
    h.y = cvt_bf16x2(v.w, v.z);
    float f0 = __uint_as_float(h.x << 16);
    float f1 = __uint_as_float(h.x & 0xffff0000u);
    float f2 = __uint_as_float(h.y << 16);
    float f3 = __uint_as_float(h.y & 0xffff0000u);
    l.x = cvt_bf16x2(v.y - f1, v.x - f0);
    l.y = cvt_bf16x2(v.w - f3, v.z - f2);
}
__device__ __forceinline__ void mma_bf16(float* c, const uint32_t* a, const uint32_t* b) {
    asm volatile(
        "mma.sync.aligned.m16n8k16.row.col.f32.bf16.bf16.f32 "
        "{%0,%1,%2,%3},{%4,%5,%6,%7},{%8,%9},{%0,%1,%2,%3};"
        : "+f"(c[0]), "+f"(c[1]), "+f"(c[2]), "+f"(c[3])
        : "r"(a[0]), "r"(a[1]), "r"(a[2]), "r"(a[3]), "r"(b[0]), "r"(b[1]));
}
__device__ __forceinline__ void ldsm_x4(uint32_t* r, uint32_t addr) {
    asm volatile("ldmatrix.sync.aligned.m8n8.x4.shared.b16 {%0,%1,%2,%3}, [%4];"
        : "=r"(r[0]), "=r"(r[1]), "=r"(r[2]), "=r"(r[3]) : "r"(addr));
}
__device__ __forceinline__ uint32_t smem_u32(const void* p) {
    uint32_t a;
    asm("{ .reg .u64 t; cvta.to.shared.u64 t, %1; cvt.u32.u64 %0, t; }"
        : "=r"(a) : "l"(p));
    return a;
}

__global__ __launch_bounds__(256)
void bf16x3_gemm_kernel(const float* __restrict__ A,   // [4096, 1024]
                        const float* __restrict__ B,   // [32000, 1024]
                        float* __restrict__ C)         // [4096, 32000]
{
    extern __shared__ __align__(16) char smem[];
    const uint32_t sb = smem_u32(smem);

    const int tid  = threadIdx.x;
    const int lane = tid & 31;
    const int warp = tid >> 5;
    const int wm   = (warp & 1) * 64;
    const int wn   = (warp >> 1) * 32;
    const int g    = lane >> 2;
    const int t    = lane & 3;

    const int mBase = blockIdx.x * 128;   // M fast-varying
    const int nBase = blockIdx.y * 128;

    // Staging: BK=32 tile is 128 rows x 8 float4. Thread owns float4 #(tid&7)
    // of rows (tid>>3)+{0,32,64,96}. float4 c4<4 -> subtile 0, c4>=4 -> subtile 1.
    const int arow = tid >> 3;            // 0..31
    const int c4   = tid & 7;             // float4 index in 32-float row
    const int sub  = c4 >> 2;             // k16 subtile
    const int scol = (c4 & 3) * 2;        // u32 col within subtile
    const float* Ag = A + (size_t)(mBase + arow) * KDIM + c4 * 4;
    const float* Bg = B + (size_t)(nBase + arow) * KDIM + c4 * 4;
    uint32_t sOff[4];
#pragma unroll
    for (int i = 0; i < 4; i++)
        sOff[i] = sub * SUB_BYTES + ((arow + i * 32) * SSTR + scol) * 4;

    // ldsm byte offsets within a subtile (verified bit-exact mapping, R13/R15)
    const int aq = lane >> 3;
    const int aRow = (lane & 7) + ((aq & 1) << 3);
    const int aCol = (aq >> 1) << 2;
    int aoff[4];
#pragma unroll
    for (int mf = 0; mf < 4; mf++)
        aoff[mf] = ((wm + mf * 16 + aRow) * SSTR + aCol) * 4;
    const int bq = lane >> 3;
    const int bRow = (lane & 7) + ((bq >> 1) << 3);
    const int bCol = (bq & 1) << 2;
    int boff[2];
#pragma unroll
    for (int p = 0; p < 2; p++)
        boff[p] = ((wn + p * 16 + bRow) * SSTR + bCol) * 4;

    float acc[4][4][4];
#pragma unroll
    for (int i = 0; i < 4; i++)
#pragma unroll
        for (int j = 0; j < 4; j++)
#pragma unroll
            for (int q = 0; q < 4; q++) acc[i][j][q] = 0.f;

    // prologue: BK32 tile 0 -> stage 0
#pragma unroll
    for (int i = 0; i < 4; i++) {
        float4 av = *reinterpret_cast<const float4*>(Ag + (size_t)i * 32 * KDIM);
        float4 bv = *reinterpret_cast<const float4*>(Bg + (size_t)i * 32 * KDIM);
        uint2 h, l;
        split4(av, h, l);
        *reinterpret_cast<uint2*>(smem + AH_OFF + sOff[i]) = h;
        *reinterpret_cast<uint2*>(smem + AL_OFF + sOff[i]) = l;
        split4(bv, h, l);
        *reinterpret_cast<uint2*>(smem + BH_OFF + sOff[i]) = h;
        *reinterpret_cast<uint2*>(smem + BL_OFF + sOff[i]) = l;
    }
    __syncthreads();

    const int NSTEP = KDIM / 32;   // 32
    for (int kt = 0; kt < NSTEP; kt++) {
        const int buf = kt & 1;
        const uint32_t stg = (uint32_t)buf * STG_BYTES;

        float4 pa[4], pb[4];
        if (kt + 1 < NSTEP) {
            const int ko = (kt + 1) * 32;
#pragma unroll
            for (int i = 0; i < 4; i++) {
                pa[i] = *reinterpret_cast<const float4*>(Ag + (size_t)i * 32 * KDIM + ko);
                pb[i] = *reinterpret_cast<const float4*>(Bg + (size_t)i * 32 * KDIM + ko);
            }
        }

        // two k16 substeps, each = verified R15 body
#pragma unroll
        for (int ks = 0; ks < 2; ks++) {
            const uint32_t su = stg + ks * SUB_BYTES;
            uint32_t afh[4][4], afl[4][4], bph[2][4], bpl[2][4];
#pragma unroll
            for (int mf = 0; mf < 4; mf++) {
                ldsm_x4(afh[mf], sb + su + AH_OFF + aoff[mf]);
                ldsm_x4(afl[mf], sb + su + AL_OFF + aoff[mf]);
            }
#pragma unroll
            for (int p = 0; p < 2; p++) {
                ldsm_x4(bph[p], sb + su + BH_OFF + boff[p]);
                ldsm_x4(bpl[p], sb + su + BL_OFF + boff[p]);
            }
#pragma unroll
            for (int mf = 0; mf < 4; mf++)
#pragma unroll
                for (int nf = 0; nf < 4; nf++) {
                    const uint32_t* bh = &bph[nf >> 1][(nf & 1) * 2];
                    const uint32_t* bl = &bpl[nf >> 1][(nf & 1) * 2];
                    mma_bf16(acc[mf][nf], afh[mf], bh);
                    mma_bf16(acc[mf][nf], afh[mf], bl);
                    mma_bf16(acc[mf][nf], afl[mf], bh);
                }
        }

        if (kt + 1 < NSTEP) {
            const uint32_t nstg = (uint32_t)(buf ^ 1) * STG_BYTES;
            // stores target buf^1: its last readers were sealed by the sync
            // at the end of iteration kt-1 -> no pre-store sync needed.
#pragma unroll
            for (int i = 0; i < 4; i++) {
                uint2 h, l;
                split4(pa[i], h, l);
                *reinterpret_cast<uint2*>(smem + nstg + AH_OFF + sOff[i]) = h;
                *reinterpret_cast<uint2*>(smem + nstg + AL_OFF + sOff[i]) = l;
                split4(pb[i], h, l);
                *reinterpret_cast<uint2*>(smem + nstg + BH_OFF + sOff[i]) = h;
                *reinterpret_cast<uint2*>(smem + nstg + BL_OFF + sOff[i]) = l;
            }
            __syncthreads();
        }
    }

    // epilogue: c0:(g,2t) c1:(g,2t+1) c2:(g+8,2t) c3:(g+8,2t+1)
#pragma unroll
    for (int mf = 0; mf < 4; mf++) {
#pragma unroll
        for (int nf = 0; nf < 4; nf++) {
            const int row = mBase + wm + mf * 16 + g;
            const int col = nBase + wn + nf * 8 + t * 2;
            float* p0 = C + (size_t)row * VOCAB + col;
            float* p1 = C + (size_t)(row + 8) * VOCAB + col;
            *reinterpret_cast<float2*>(p0) = make_float2(acc[mf][nf][0], acc[mf][nf][1]);
            *reinterpret_cast<float2*>(p1) = make_float2(acc[mf][nf][2], acc[mf][nf][3]);
        }
    }
}

// ---------------------------------------------------------------------------
// 4) logit_w: ONLINE single-pass softmax (reads logit once, not twice)
//    + projection onto +-1 bit codes.
// ---------------------------------------------------------------------------
__global__ __launch_bounds__(256)
void softmax_bits_kernel(const float* __restrict__ logit,
                         float* __restrict__ out_lw)
{
    const int row = blockIdx.x;
    const int tid = threadIdx.x;
    const float* L = logit + (size_t)row * VOCAB;

    // online: running max m, sum s, 7 high-bit sums; rescale on new max
    float m = -1e30f, s = 0.f;
    float bh[7] = {0.f, 0.f, 0.f, 0.f, 0.f, 0.f, 0.f};
    for (int tt = 0; tt < VOCAB / 256; tt++) {
        float x = L[tid + (tt << 8)];
        if (x > m) {
            float f = __expf(m - x);
            s *= f;
#pragma unroll
            for (int k = 0; k < 7; k++) bh[k] *= f;
            m = x;
        }
        float e = __expf(x - m);
        s += e;
#pragma unroll
        for (int k = 0; k < 7; k++)
            bh[k] += ((tt >> k) & 1) ? e : 0.f;
    }

    // block max, then rescale thread-local accumulators to global max
    float M = m;
#pragma unroll
    for (int o = 16; o; o >>= 1) M = fmaxf(M, __shfl_xor_sync(0xffffffffu, M, o));
    __shared__ float wmax[8];
    if ((tid & 31) == 0) wmax[tid >> 5] = M;
    __syncthreads();
    M = wmax[0];
#pragma unroll
    for (int w = 1; w < 8; w++) M = fmaxf(M, wmax[w]);
    {
        float f = __expf(m - M);
        s *= f;
#pragma unroll
        for (int k = 0; k < 7; k++) bh[k] *= f;
    }

    float bs[16];
#pragma unroll
    for (int k = 0; k < 8; k++) bs[k] = ((tid >> k) & 1) ? s : 0.f;
#pragma unroll
    for (int k = 0; k < 7; k++) bs[k + 8] = bh[k];
    bs[15] = s;

#pragma unroll
    for (int q = 0; q < 16; q++) {
#pragma unroll
        for (int o = 16; o; o >>= 1)
            bs[q] += __shfl_xor_sync(0xffffffffu, bs[q], o);
    }
    __shared__ float red[8][16];
    if ((tid & 31) == 0) {
#pragma unroll
        for (int q = 0; q < 16; q++) red[tid >> 5][q] = bs[q];
    }
    __syncthreads();
    if (tid == 0) {
        float tot[16];
#pragma unroll
        for (int q = 0; q < 16; q++) {
            float v = 0.f;
#pragma unroll
            for (int w = 0; w < 8; w++) v += red[w][q];
            tot[q] = v;
        }
        float inv = 1.0f / tot[15];
#pragma unroll
        for (int k = 0; k < 15; k++)
            out_lw[(size_t)row * NBITS + (14 - k)] = 2.0f * tot[k] * inv - 1.0f;
    }
}

// ---------------------------------------------------------------------------
extern "C" void kernel_launch(void* const* d_in, const int* in_sizes, int n_in,
                              void* d_out, int out_size)
{
    const int*   ids    = (const int*)  d_in[0];
    const float* tensor = (const float*)d_in[1];
    const float* weight = (const float*)d_in[2];
    const float* wbit   = (const float*)d_in[3];

    float* out     = (float*)d_out;
    float* id_emb  = out;
    float* bit_emb = out + OFF_BIT;
    float* logit   = out + OFF_LOGIT;
    float* lw      = out + OFF_LW;

    id_embed_kernel <<<4096, 256>>>(ids, weight, id_emb);
    bit_embed_kernel<<<4096, 256>>>(ids, wbit, bit_emb);

    cudaFuncSetAttribute(bf16x3_gemm_kernel,
                         cudaFuncAttributeMaxDynamicSharedMemorySize, GEMM_SMEM);
    dim3 grid(NTOK / 128, VOCAB / 128);   // (32 M fast, 250 N): A L2-resident
    bf16x3_gemm_kernel<<<grid, 256, GEMM_SMEM>>>(tensor, weight, logit);

    softmax_bits_kernel<<<NTOK, 256>>>(logit, lw);
}